// round 1
// baseline (speedup 1.0000x reference)
#include <cuda_runtime.h>

#define NNODE  100000
#define NEDGE  1600000
#define EPLUS  (NEDGE + NNODE)
#define GBATCH 64

// ---------------- scratch (device globals; no allocation allowed) -----------
__device__ float g_h1  [NNODE * 128];
__device__ float g_agg1[NNODE * 128];
__device__ float g_h2  [NNODE * 64];
__device__ float g_agg2[NNODE * 64];
__device__ float g_esrc1[NNODE * 2];
__device__ float g_edst1[NNODE * 2];
__device__ float g_esrc2[NNODE];
__device__ float g_edst2[NNODE];
__device__ float g_we1[EPLUS * 2];
__device__ float g_we2[EPLUS];
__device__ float g_den1[NNODE * 2];
__device__ float g_den2[NNODE];
__device__ float g_pool[GBATCH * 64];
__device__ float g_cnt [GBATCH];

// ---------------- helpers ---------------------------------------------------
__device__ __forceinline__ float lrelu(float v) { return v > 0.f ? v : 0.2f * v; }

__device__ __forceinline__ void red_add_v4(float* p, float4 v) {
    asm volatile("red.global.add.v4.f32 [%0], {%1,%2,%3,%4};"
                 :: "l"(p), "f"(v.x), "f"(v.y), "f"(v.z), "f"(v.w) : "memory");
}
__device__ __forceinline__ void red_add_v2(float* p, float a, float b) {
    asm volatile("red.global.add.v2.f32 [%0], {%1,%2};"
                 :: "l"(p), "f"(a), "f"(b) : "memory");
}

// ---------------- zero scratch ----------------------------------------------
__global__ void zero_kernel() {
    int i = blockIdx.x * blockDim.x + threadIdx.x;
    int stride = gridDim.x * blockDim.x;
    for (int k = i; k < NNODE * 128; k += stride) g_agg1[k] = 0.f;
    for (int k = i; k < NNODE * 64;  k += stride) g_agg2[k] = 0.f;
    for (int k = i; k < NNODE * 2;   k += stride) g_den1[k] = 0.f;
    for (int k = i; k < NNODE;       k += stride) g_den2[k] = 0.f;
    if (i < GBATCH * 64) g_pool[i] = 0.f;
    if (i < GBATCH)      g_cnt[i]  = 0.f;
}

// ---------------- GEMM: Y[n,NCOL] = f(X)[n,128] @ W[128,NCOL] ---------------
// Block: NCOL threads, 32 rows per block. W fully resident in smem.
template <int NCOL, bool PRERELU>
__global__ void __launch_bounds__(NCOL) gemm_rows(
    const float* __restrict__ X, const float* __restrict__ W,
    const float* __restrict__ prebias, float* __restrict__ Y, int n)
{
    extern __shared__ float sm[];
    float* sW = sm;                 // 128*NCOL
    float* sX = sm + 128 * NCOL;    // 32*128
    const int t = threadIdx.x;

    for (int i = t; i < 128 * NCOL; i += NCOL) sW[i] = W[i];

    const int row0 = blockIdx.x * 32;
    for (int i = t; i < 32 * 128; i += NCOL) {
        int r = i >> 7, c = i & 127;
        int gr = row0 + r;
        float v = (gr < n) ? X[gr * 128 + c] : 0.f;
        if (PRERELU) v = fmaxf(v + prebias[c], 0.f);
        sX[i] = v;
    }
    __syncthreads();

    float acc[32];
#pragma unroll
    for (int i = 0; i < 32; i++) acc[i] = 0.f;

    const float4* sX4 = (const float4*)sX;
#pragma unroll 2
    for (int k4 = 0; k4 < 32; k4++) {
        float w0 = sW[(4 * k4 + 0) * NCOL + t];
        float w1 = sW[(4 * k4 + 1) * NCOL + t];
        float w2 = sW[(4 * k4 + 2) * NCOL + t];
        float w3 = sW[(4 * k4 + 3) * NCOL + t];
#pragma unroll
        for (int i = 0; i < 32; i++) {
            float4 xv = sX4[i * 32 + k4];
            acc[i] = fmaf(xv.x, w0, acc[i]);
            acc[i] = fmaf(xv.y, w1, acc[i]);
            acc[i] = fmaf(xv.z, w2, acc[i]);
            acc[i] = fmaf(xv.w, w3, acc[i]);
        }
    }

    for (int i = 0; i < 32; i++) {
        int gr = row0 + i;
        if (gr < n) Y[gr * NCOL + t] = acc[i];
    }
}

// ---------------- attention-logit scores: e_src/e_dst per node --------------
template <int NCOL>
__global__ void escore_kernel(const float* __restrict__ H,
                              const float* __restrict__ asrc,
                              const float* __restrict__ adst,
                              float* __restrict__ esrc,
                              float* __restrict__ edst, int n)
{
    int gw = (blockIdx.x * blockDim.x + threadIdx.x) >> 5;
    int lane = threadIdx.x & 31;
    if (gw >= n) return;

    if (NCOL == 128) {   // 2 heads x 64: lanes 0-15 head0, 16-31 head1
        float4 h  = *(const float4*)&H[gw * 128 + lane * 4];
        float4 as = *(const float4*)&asrc[lane * 4];
        float4 ad = *(const float4*)&adst[lane * 4];
        float ps = h.x * as.x + h.y * as.y + h.z * as.z + h.w * as.w;
        float pd = h.x * ad.x + h.y * ad.y + h.z * ad.z + h.w * ad.w;
#pragma unroll
        for (int o = 8; o >= 1; o >>= 1) {
            ps += __shfl_xor_sync(0xffffffffu, ps, o);
            pd += __shfl_xor_sync(0xffffffffu, pd, o);
        }
        if ((lane & 15) == 0) {
            esrc[gw * 2 + (lane >> 4)] = ps;
            edst[gw * 2 + (lane >> 4)] = pd;
        }
    } else {             // 1 head x 64
        float2 h  = *(const float2*)&H[gw * 64 + lane * 2];
        float2 as = *(const float2*)&asrc[lane * 2];
        float2 ad = *(const float2*)&adst[lane * 2];
        float ps = h.x * as.x + h.y * as.y;
        float pd = h.x * ad.x + h.y * ad.y;
#pragma unroll
        for (int o = 16; o >= 1; o >>= 1) {
            ps += __shfl_xor_sync(0xffffffffu, ps, o);
            pd += __shfl_xor_sync(0xffffffffu, pd, o);
        }
        if (lane == 0) { esrc[gw] = ps; edst[gw] = pd; }
    }
}

// ---------------- edge exp + denom (layer 1, 2 heads) -----------------------
__global__ void edge_exp1_kernel(const int* __restrict__ ei)
{
    int e = blockIdx.x * blockDim.x + threadIdx.x;
    if (e >= EPLUS) return;
    int s, d;
    if (e < NEDGE) { s = ei[e]; d = ei[NEDGE + e]; } else { s = e - NEDGE; d = s; }
    float2 es = *(const float2*)&g_esrc1[2 * s];
    float2 ed = *(const float2*)&g_edst1[2 * d];
    float w0 = __expf(lrelu(es.x + ed.x));
    float w1 = __expf(lrelu(es.y + ed.y));
    *(float2*)&g_we1[2 * e] = make_float2(w0, w1);
    red_add_v2(&g_den1[2 * d], w0, w1);
}

// ---------------- edge message aggregation (layer 1): warp per edge ---------
__global__ void edge_msg1_kernel(const int* __restrict__ ei)
{
    int gt = blockIdx.x * blockDim.x + threadIdx.x;
    int e = gt >> 5, lane = gt & 31;
    if (e >= EPLUS) return;
    int s, d;
    if (e < NEDGE) { s = ei[e]; d = ei[NEDGE + e]; } else { s = e - NEDGE; d = s; }
    float2 w  = *(const float2*)&g_we1[2 * e];
    float2 dn = *(const float2*)&g_den1[2 * d];
    float alpha = (lane < 16) ? __fdividef(w.x, dn.x) : __fdividef(w.y, dn.y);
    float4 h = *(const float4*)&g_h1[s * 128 + lane * 4];
    red_add_v4(&g_agg1[d * 128 + lane * 4],
               make_float4(h.x * alpha, h.y * alpha, h.z * alpha, h.w * alpha));
}

// ---------------- edge exp + denom (layer 2, 1 head) ------------------------
__global__ void edge_exp2_kernel(const int* __restrict__ ei)
{
    int e = blockIdx.x * blockDim.x + threadIdx.x;
    if (e >= EPLUS) return;
    int s, d;
    if (e < NEDGE) { s = ei[e]; d = ei[NEDGE + e]; } else { s = e - NEDGE; d = s; }
    float w = __expf(lrelu(g_esrc2[s] + g_edst2[d]));
    g_we2[e] = w;
    atomicAdd(&g_den2[d], w);
}

// ---------------- edge message aggregation (layer 2): 16 lanes per edge -----
__global__ void edge_msg2_kernel(const int* __restrict__ ei)
{
    int gt = blockIdx.x * blockDim.x + threadIdx.x;
    int e = gt >> 4, lane = gt & 15;
    if (e >= EPLUS) return;
    int s, d;
    if (e < NEDGE) { s = ei[e]; d = ei[NEDGE + e]; } else { s = e - NEDGE; d = s; }
    float alpha = __fdividef(g_we2[e], g_den2[d]);
    float4 h = *(const float4*)&g_h2[s * 64 + lane * 4];
    red_add_v4(&g_agg2[d * 64 + lane * 4],
               make_float4(h.x * alpha, h.y * alpha, h.z * alpha, h.w * alpha));
}

// ---------------- global mean pool (sum + count) ----------------------------
__global__ void pool_kernel(const int* __restrict__ batch)
{
    int gt = blockIdx.x * blockDim.x + threadIdx.x;
    int nidx = gt >> 4, lane = gt & 15;
    if (nidx >= NNODE) return;
    int g = batch[nidx];
    float4 v = *(const float4*)&g_agg2[nidx * 64 + lane * 4];
    red_add_v4(&g_pool[g * 64 + lane * 4], v);
    if (lane == 0) atomicAdd(&g_cnt[g], 1.f);
}

// ---------------- decoder MLP (single block) --------------------------------
__global__ void __launch_bounds__(256) mlp_kernel(
    const float* __restrict__ b2,
    const float* __restrict__ dw1, const float* __restrict__ db1,
    const float* __restrict__ dw2, const float* __restrict__ db2,
    float* __restrict__ out)
{
    __shared__ float sp[64 * 64];
    __shared__ float sz[64 * 64];
    int t = threadIdx.x;
    for (int i = t; i < 4096; i += 256) {
        int g = i >> 6, c = i & 63;
        sp[i] = g_pool[i] / fmaxf(g_cnt[g], 1.f) + b2[c];
    }
    __syncthreads();
    int j = t & 63, gq = t >> 6;
    for (int g = gq; g < 64; g += 4) {
        float a = db1[j];
#pragma unroll 8
        for (int c = 0; c < 64; c++) a = fmaf(sp[g * 64 + c], dw1[c * 64 + j], a);
        sz[g * 64 + j] = fmaxf(a, 0.f);
    }
    __syncthreads();
    for (int i = t; i < 64 * 16; i += 256) {
        int g = i >> 4, o = i & 15;
        float a = db2[o];
#pragma unroll 8
        for (int jj = 0; jj < 64; jj++) a = fmaf(sz[g * 64 + jj], dw2[jj * 16 + o], a);
        out[i] = a;
    }
}

// ---------------- launch ----------------------------------------------------
extern "C" void kernel_launch(void* const* d_in, const int* in_sizes, int n_in,
                              void* d_out, int out_size)
{
    const float* x    = (const float*)d_in[0];
    const int*   ei   = (const int*)  d_in[1];
    const int*   batch= (const int*)  d_in[2];
    const float* W1   = (const float*)d_in[3];
    const float* as1  = (const float*)d_in[4];
    const float* ad1  = (const float*)d_in[5];
    const float* b1   = (const float*)d_in[6];
    const float* W2   = (const float*)d_in[7];
    const float* as2  = (const float*)d_in[8];
    const float* ad2  = (const float*)d_in[9];
    const float* b2   = (const float*)d_in[10];
    const float* dw1  = (const float*)d_in[11];
    const float* db1  = (const float*)d_in[12];
    const float* dw2  = (const float*)d_in[13];
    const float* db2  = (const float*)d_in[14];
    float* out = (float*)d_out;

    float *h1p, *agg1p, *h2p, *agg2p, *es1p, *ed1p, *es2p, *ed2p;
    cudaGetSymbolAddress((void**)&h1p,   g_h1);
    cudaGetSymbolAddress((void**)&agg1p, g_agg1);
    cudaGetSymbolAddress((void**)&h2p,   g_h2);
    cudaGetSymbolAddress((void**)&agg2p, g_agg2);
    cudaGetSymbolAddress((void**)&es1p,  g_esrc1);
    cudaGetSymbolAddress((void**)&ed1p,  g_edst1);
    cudaGetSymbolAddress((void**)&es2p,  g_esrc2);
    cudaGetSymbolAddress((void**)&ed2p,  g_edst2);

    const int smem1 = (128 * 128 + 32 * 128) * (int)sizeof(float);  // 80 KB
    const int smem2 = (128 * 64 + 32 * 128) * (int)sizeof(float);   // 48 KB
    cudaFuncSetAttribute(gemm_rows<128, false>,
                         cudaFuncAttributeMaxDynamicSharedMemorySize, smem1);
    cudaFuncSetAttribute(gemm_rows<64, true>,
                         cudaFuncAttributeMaxDynamicSharedMemorySize, smem2);

    const int nblk_rows = (NNODE + 31) / 32;                 // 3125
    const int warp_blocks = (NNODE * 32 + 255) / 256;        // escore: warp/node
    const int edge_blocks = (EPLUS + 255) / 256;
    const int msg1_blocks = ((long long)EPLUS * 32 + 255) / 256;
    const int msg2_blocks = ((long long)EPLUS * 16 + 255) / 256;
    const int pool_blocks = (NNODE * 16 + 255) / 256;

    zero_kernel<<<2048, 256>>>();

    // ----- layer 1 -----
    gemm_rows<128, false><<<nblk_rows, 128, smem1>>>(x, W1, nullptr, h1p, NNODE);
    escore_kernel<128><<<warp_blocks, 256>>>(h1p, as1, ad1, es1p, ed1p, NNODE);
    edge_exp1_kernel<<<edge_blocks, 256>>>(ei);
    edge_msg1_kernel<<<msg1_blocks, 256>>>(ei);

    // ----- layer 2 (relu(agg1+b1) fused into GEMM2 input) -----
    gemm_rows<64, true><<<nblk_rows, 64, smem2>>>(agg1p, W2, b1, h2p, NNODE);
    escore_kernel<64><<<warp_blocks, 256>>>(h2p, as2, ad2, es2p, ed2p, NNODE);
    edge_exp2_kernel<<<edge_blocks, 256>>>(ei);
    edge_msg2_kernel<<<msg2_blocks, 256>>>(ei);

    // ----- pool + decoder -----
    pool_kernel<<<pool_blocks, 256>>>(batch);
    mlp_kernel<<<1, 256>>>(b2, dw1, db1, dw2, db2, out);
}

// round 2
// speedup vs baseline: 1.3721x; 1.3721x over previous
#include <cuda_runtime.h>

#define NNODE  100000
#define NEDGE  1600000
#define EPLUS  (NEDGE + NNODE)
#define GBATCH 64
#define NBLK_SCAN 98   // ceil(NNODE/1024)
#define FULLMASK 0xffffffffu

// ---------------- scratch (device globals) ----------------------------------
__device__ float g_h1  [NNODE * 128];
__device__ float g_agg1[NNODE * 128];
__device__ float g_h2  [NNODE * 64];
__device__ float g_esrc1[NNODE * 2];
__device__ float g_edst1[NNODE * 2];
__device__ float g_esrc2[NNODE];
__device__ float g_edst2[NNODE];
__device__ float g_pool[GBATCH * 64];
__device__ int   g_deg [NNODE];
__device__ int   g_off [NNODE];
__device__ int   g_cur [NNODE];
__device__ int   g_srcs[EPLUS];
__device__ int   g_blocksum[128];

// ---------------- helpers ---------------------------------------------------
__device__ __forceinline__ float lrelu(float v) { return v > 0.f ? v : 0.2f * v; }

__device__ __forceinline__ void red_add_v2(float* p, float a, float b) {
    asm volatile("red.global.add.v2.f32 [%0], {%1,%2};"
                 :: "l"(p), "f"(a), "f"(b) : "memory");
}

// ---------------- CSR build --------------------------------------------------
__global__ void init_kernel() {
    int i = blockIdx.x * blockDim.x + threadIdx.x;
    if (i < NNODE) g_deg[i] = 1;            // self loop
    if (i < GBATCH * 64) g_pool[i] = 0.f;
}

__global__ void deg_count_kernel(const int* __restrict__ ei) {
    int e = blockIdx.x * blockDim.x + threadIdx.x;
    if (e < NEDGE) atomicAdd(&g_deg[ei[NEDGE + e]], 1);
}

__global__ void __launch_bounds__(1024) scan1_kernel() {
    __shared__ int sh[1024];
    int t = threadIdx.x, i = blockIdx.x * 1024 + t;
    int v = (i < NNODE) ? g_deg[i] : 0;
    sh[t] = v; __syncthreads();
    for (int o = 1; o < 1024; o <<= 1) {
        int add = (t >= o) ? sh[t - o] : 0;
        __syncthreads(); sh[t] += add; __syncthreads();
    }
    if (i < NNODE) g_off[i] = sh[t] - v;    // exclusive (block-local)
    if (t == 1023) g_blocksum[blockIdx.x] = sh[t];
}

__global__ void __launch_bounds__(128) scan2_kernel() {
    __shared__ int sh[128];
    int t = threadIdx.x;
    int v = (t < NBLK_SCAN) ? g_blocksum[t] : 0;
    sh[t] = v; __syncthreads();
    for (int o = 1; o < 128; o <<= 1) {
        int add = (t >= o) ? sh[t - o] : 0;
        __syncthreads(); sh[t] += add; __syncthreads();
    }
    g_blocksum[t] = sh[t] - v;              // exclusive block offsets
}

__global__ void scan3_kernel() {
    int i = blockIdx.x * blockDim.x + threadIdx.x;
    if (i < NNODE) { g_off[i] += g_blocksum[i >> 10]; g_cur[i] = 0; }
}

__global__ void fill_kernel(const int* __restrict__ ei) {
    int e = blockIdx.x * blockDim.x + threadIdx.x;
    if (e >= EPLUS) return;
    int s, d;
    if (e < NEDGE) { s = ei[e]; d = ei[NEDGE + e]; } else { s = e - NEDGE; d = s; }
    int pos = g_off[d] + atomicAdd(&g_cur[d], 1);
    g_srcs[pos] = s;
}

// ---------------- GEMM: Y[n,NCOL] = f(X)[n,128] @ W[128,NCOL] ----------------
template <int NCOL, bool PRERELU>
__global__ void __launch_bounds__(NCOL) gemm_rows(
    const float* __restrict__ X, const float* __restrict__ W,
    const float* __restrict__ prebias, float* __restrict__ Y, int n)
{
    extern __shared__ float sm[];
    float* sW = sm;                 // 128*NCOL
    float* sX = sm + 128 * NCOL;    // 32*128
    const int t = threadIdx.x;

    for (int i = t; i < 128 * NCOL; i += NCOL) sW[i] = W[i];

    const int row0 = blockIdx.x * 32;
    for (int i = t; i < 32 * 128; i += NCOL) {
        int r = i >> 7, c = i & 127;
        int gr = row0 + r;
        float v = (gr < n) ? X[gr * 128 + c] : 0.f;
        if (PRERELU) v = fmaxf(v + prebias[c], 0.f);
        sX[i] = v;
    }
    __syncthreads();

    float acc[32];
#pragma unroll
    for (int i = 0; i < 32; i++) acc[i] = 0.f;

    const float4* sX4 = (const float4*)sX;
#pragma unroll 2
    for (int k4 = 0; k4 < 32; k4++) {
        float w0 = sW[(4 * k4 + 0) * NCOL + t];
        float w1 = sW[(4 * k4 + 1) * NCOL + t];
        float w2 = sW[(4 * k4 + 2) * NCOL + t];
        float w3 = sW[(4 * k4 + 3) * NCOL + t];
#pragma unroll
        for (int i = 0; i < 32; i++) {
            float4 xv = sX4[i * 32 + k4];
            acc[i] = fmaf(xv.x, w0, acc[i]);
            acc[i] = fmaf(xv.y, w1, acc[i]);
            acc[i] = fmaf(xv.z, w2, acc[i]);
            acc[i] = fmaf(xv.w, w3, acc[i]);
        }
    }

    for (int i = 0; i < 32; i++) {
        int gr = row0 + i;
        if (gr < n) Y[gr * NCOL + t] = acc[i];
    }
}

// ---------------- attention-logit scores -------------------------------------
template <int NCOL>
__global__ void escore_kernel(const float* __restrict__ H,
                              const float* __restrict__ asrc,
                              const float* __restrict__ adst,
                              float* __restrict__ esrc,
                              float* __restrict__ edst, int n)
{
    int gw = (blockIdx.x * blockDim.x + threadIdx.x) >> 5;
    int lane = threadIdx.x & 31;
    if (gw >= n) return;

    if (NCOL == 128) {   // 2 heads x 64
        float4 h  = *(const float4*)&H[gw * 128 + lane * 4];
        float4 as = *(const float4*)&asrc[lane * 4];
        float4 ad = *(const float4*)&adst[lane * 4];
        float ps = h.x * as.x + h.y * as.y + h.z * as.z + h.w * as.w;
        float pd = h.x * ad.x + h.y * ad.y + h.z * ad.z + h.w * ad.w;
#pragma unroll
        for (int o = 8; o >= 1; o >>= 1) {
            ps += __shfl_xor_sync(FULLMASK, ps, o);
            pd += __shfl_xor_sync(FULLMASK, pd, o);
        }
        if ((lane & 15) == 0) {
            esrc[gw * 2 + (lane >> 4)] = ps;
            edst[gw * 2 + (lane >> 4)] = pd;
        }
    } else {             // 1 head x 64
        float2 h  = *(const float2*)&H[gw * 64 + lane * 2];
        float2 as = *(const float2*)&asrc[lane * 2];
        float2 ad = *(const float2*)&adst[lane * 2];
        float ps = h.x * as.x + h.y * as.y;
        float pd = h.x * ad.x + h.y * ad.y;
#pragma unroll
        for (int o = 16; o >= 1; o >>= 1) {
            ps += __shfl_xor_sync(FULLMASK, ps, o);
            pd += __shfl_xor_sync(FULLMASK, pd, o);
        }
        if (lane == 0) { esrc[gw] = ps; edst[gw] = pd; }
    }
}

// ---------------- layer-1 gather: warp per destination node ------------------
__global__ void __launch_bounds__(256) gather1_kernel()
{
    int warp = (blockIdx.x * blockDim.x + threadIdx.x) >> 5;
    int lane = threadIdx.x & 31;
    if (warp >= NNODE) return;
    const int n = warp;
    const int base = g_off[n];
    const int m = g_deg[n];
    float2 ed = *(const float2*)&g_edst1[2 * n];

    float4 acc = make_float4(0.f, 0.f, 0.f, 0.f);
    float den0 = 0.f, den1 = 0.f;

    for (int k0 = 0; k0 < m; k0 += 32) {
        int kk = k0 + lane;
        int s = 0; float w0 = 0.f, w1 = 0.f;
        if (kk < m) {
            s = g_srcs[base + kk];
            float2 es = *(const float2*)&g_esrc1[2 * s];
            w0 = __expf(lrelu(es.x + ed.x));
            w1 = __expf(lrelu(es.y + ed.y));
        }
        den0 += w0; den1 += w1;
        int cnt = min(32, m - k0);
#pragma unroll 4
        for (int j = 0; j < cnt; j++) {
            int   sj  = __shfl_sync(FULLMASK, s,  j);
            float w0j = __shfl_sync(FULLMASK, w0, j);
            float w1j = __shfl_sync(FULLMASK, w1, j);
            float w = (lane < 16) ? w0j : w1j;
            float4 h = *(const float4*)&g_h1[sj * 128 + lane * 4];
            acc.x = fmaf(w, h.x, acc.x);
            acc.y = fmaf(w, h.y, acc.y);
            acc.z = fmaf(w, h.z, acc.z);
            acc.w = fmaf(w, h.w, acc.w);
        }
    }
#pragma unroll
    for (int o = 16; o >= 1; o >>= 1) {
        den0 += __shfl_xor_sync(FULLMASK, den0, o);
        den1 += __shfl_xor_sync(FULLMASK, den1, o);
    }
    float inv = __fdividef(1.f, (lane < 16) ? den0 : den1);
    *(float4*)&g_agg1[n * 128 + lane * 4] =
        make_float4(acc.x * inv, acc.y * inv, acc.z * inv, acc.w * inv);
}

// ---------------- layer-2 gather + fused mean-pool accumulation --------------
__global__ void __launch_bounds__(256) gather2_kernel(const int* __restrict__ batch)
{
    int warp = (blockIdx.x * blockDim.x + threadIdx.x) >> 5;
    int lane = threadIdx.x & 31;
    if (warp >= NNODE) return;
    const int n = warp;
    const int base = g_off[n];
    const int m = g_deg[n];
    float ed = g_edst2[n];

    float2 acc = make_float2(0.f, 0.f);
    float den = 0.f;

    for (int k0 = 0; k0 < m; k0 += 32) {
        int kk = k0 + lane;
        int s = 0; float w = 0.f;
        if (kk < m) {
            s = g_srcs[base + kk];
            w = __expf(lrelu(g_esrc2[s] + ed));
        }
        den += w;
        int cnt = min(32, m - k0);
#pragma unroll 4
        for (int j = 0; j < cnt; j++) {
            int   sj = __shfl_sync(FULLMASK, s, j);
            float wj = __shfl_sync(FULLMASK, w, j);
            float2 h = *(const float2*)&g_h2[sj * 64 + lane * 2];
            acc.x = fmaf(wj, h.x, acc.x);
            acc.y = fmaf(wj, h.y, acc.y);
        }
    }
#pragma unroll
    for (int o = 16; o >= 1; o >>= 1)
        den += __shfl_xor_sync(FULLMASK, den, o);
    float inv = __fdividef(1.f, den);
    // fused pooling: agg2 never hits memory
    int g = batch[n];
    red_add_v2(&g_pool[g * 64 + lane * 2], acc.x * inv, acc.y * inv);
}

// ---------------- decoder MLP (single block) ---------------------------------
__global__ void __launch_bounds__(256) mlp_kernel(
    const int* __restrict__ batch,
    const float* __restrict__ b2,
    const float* __restrict__ dw1, const float* __restrict__ db1,
    const float* __restrict__ dw2, const float* __restrict__ db2,
    float* __restrict__ out)
{
    __shared__ float sp[64 * 64];
    __shared__ float sz[64 * 64];
    __shared__ float scnt[64];
    int t = threadIdx.x;

    if (t < 65) {
        // lower_bound(batch, t): first idx with batch[idx] >= t
        int lo = 0, hi = NNODE;
        while (lo < hi) { int mid = (lo + hi) >> 1; if (batch[mid] < t) lo = mid + 1; else hi = mid; }
        if (t < 64) scnt[t] = 0.f;   // placeholder, fixed below
        sz[t] = (float)lo;           // reuse sz as temp boundary storage
    }
    __syncthreads();
    if (t < 64) {
        float c = sz[t + 1] - sz[t];
        scnt[t] = fmaxf(c, 1.f);
    }
    __syncthreads();

    for (int i = t; i < 4096; i += 256) {
        int g = i >> 6, c = i & 63;
        sp[i] = g_pool[i] / scnt[g] + b2[c];
    }
    __syncthreads();
    int j = t & 63, gq = t >> 6;
    for (int g = gq; g < 64; g += 4) {
        float a = db1[j];
#pragma unroll 8
        for (int c = 0; c < 64; c++) a = fmaf(sp[g * 64 + c], dw1[c * 64 + j], a);
        sz[g * 64 + j] = fmaxf(a, 0.f);
    }
    __syncthreads();
    for (int i = t; i < 64 * 16; i += 256) {
        int g = i >> 4, o = i & 15;
        float a = db2[o];
#pragma unroll 8
        for (int jj = 0; jj < 64; jj++) a = fmaf(sz[g * 64 + jj], dw2[jj * 16 + o], a);
        out[i] = a;
    }
}

// ---------------- launch ----------------------------------------------------
extern "C" void kernel_launch(void* const* d_in, const int* in_sizes, int n_in,
                              void* d_out, int out_size)
{
    const float* x    = (const float*)d_in[0];
    const int*   ei   = (const int*)  d_in[1];
    const int*   batch= (const int*)  d_in[2];
    const float* W1   = (const float*)d_in[3];
    const float* as1  = (const float*)d_in[4];
    const float* ad1  = (const float*)d_in[5];
    const float* b1   = (const float*)d_in[6];
    const float* W2   = (const float*)d_in[7];
    const float* as2  = (const float*)d_in[8];
    const float* ad2  = (const float*)d_in[9];
    const float* b2   = (const float*)d_in[10];
    const float* dw1  = (const float*)d_in[11];
    const float* db1  = (const float*)d_in[12];
    const float* dw2  = (const float*)d_in[13];
    const float* db2  = (const float*)d_in[14];
    float* out = (float*)d_out;

    float *h1p, *agg1p, *h2p, *es1p, *ed1p, *es2p, *ed2p;
    cudaGetSymbolAddress((void**)&h1p,   g_h1);
    cudaGetSymbolAddress((void**)&agg1p, g_agg1);
    cudaGetSymbolAddress((void**)&h2p,   g_h2);
    cudaGetSymbolAddress((void**)&es1p,  g_esrc1);
    cudaGetSymbolAddress((void**)&ed1p,  g_edst1);
    cudaGetSymbolAddress((void**)&es2p,  g_esrc2);
    cudaGetSymbolAddress((void**)&ed2p,  g_edst2);

    const int smem1 = (128 * 128 + 32 * 128) * (int)sizeof(float);
    const int smem2 = (128 * 64 + 32 * 128) * (int)sizeof(float);
    cudaFuncSetAttribute(gemm_rows<128, false>,
                         cudaFuncAttributeMaxDynamicSharedMemorySize, smem1);
    cudaFuncSetAttribute(gemm_rows<64, true>,
                         cudaFuncAttributeMaxDynamicSharedMemorySize, smem2);

    const int nblk_rows  = (NNODE + 31) / 32;
    const int node_blk   = (NNODE + 255) / 256;
    const int warp_blocks= (NNODE * 32 + 255) / 256;
    const int edge_blocks= (NEDGE + 255) / 256;
    const int eplus_blocks = (EPLUS + 255) / 256;
    const int gath_blocks  = (NNODE * 32 + 255) / 256;

    // ----- CSR build (shared by both layers) -----
    init_kernel<<<node_blk, 256>>>();
    deg_count_kernel<<<edge_blocks, 256>>>(ei);
    scan1_kernel<<<NBLK_SCAN, 1024>>>();
    scan2_kernel<<<1, 128>>>();
    scan3_kernel<<<node_blk, 256>>>();
    fill_kernel<<<eplus_blocks, 256>>>(ei);

    // ----- layer 1 -----
    gemm_rows<128, false><<<nblk_rows, 128, smem1>>>(x, W1, nullptr, h1p, NNODE);
    escore_kernel<128><<<warp_blocks, 256>>>(h1p, as1, ad1, es1p, ed1p, NNODE);
    gather1_kernel<<<gath_blocks, 256>>>();

    // ----- layer 2 -----
    gemm_rows<64, true><<<nblk_rows, 64, smem2>>>(agg1p, W2, b1, h2p, NNODE);
    escore_kernel<64><<<warp_blocks, 256>>>(h2p, as2, ad2, es2p, ed2p, NNODE);
    gather2_kernel<<<gath_blocks, 256>>>(batch);

    // ----- decoder -----
    mlp_kernel<<<1, 256>>>(batch, b2, dw1, db1, dw2, db2, out);
}

// round 3
// speedup vs baseline: 1.4772x; 1.0766x over previous
#include <cuda_runtime.h>
#include <cuda_fp16.h>

#define NNODE  100000
#define NEDGE  1600000
#define EPLUS  (NEDGE + NNODE)
#define GBATCH 64
#define NBLK_SCAN 98
#define FULLMASK 0xffffffffu

// ---------------- scratch ----------------------------------------------------
__device__ float  g_h1  [NNODE * 128];
__device__ float  g_agg1[NNODE * 128];
__device__ float  g_h2  [NNODE * 64];
__device__ __half g_h1h [NNODE * 128];
__device__ __half g_h2h [NNODE * 64];
__device__ float  g_esrc1[NNODE * 2];
__device__ float  g_edst1[NNODE * 2];
__device__ float  g_esrc2[NNODE];
__device__ float  g_edst2[NNODE];
__device__ float  g_pool[GBATCH * 64];
__device__ int    g_deg [NNODE];
__device__ int    g_off [NNODE];
__device__ int    g_cur [NNODE];
__device__ int    g_srcs[EPLUS];
__device__ int    g_blocksum[128];

// ---------------- helpers ----------------------------------------------------
__device__ __forceinline__ float lrelu(float v) { return v > 0.f ? v : 0.2f * v; }

__device__ __forceinline__ void red_add_v2(float* p, float a, float b) {
    asm volatile("red.global.add.v2.f32 [%0], {%1,%2};"
                 :: "l"(p), "f"(a), "f"(b) : "memory");
}

// ---------------- CSR build ---------------------------------------------------
__global__ void init_kernel() {
    int i = blockIdx.x * blockDim.x + threadIdx.x;
    if (i < NNODE) g_deg[i] = 1;
    if (i < GBATCH * 64) g_pool[i] = 0.f;
}

__global__ void deg_count_kernel(const int* __restrict__ ei) {
    int e = blockIdx.x * blockDim.x + threadIdx.x;
    if (e < NEDGE) atomicAdd(&g_deg[ei[NEDGE + e]], 1);
}

__global__ void __launch_bounds__(1024) scan1_kernel() {
    __shared__ int sh[1024];
    int t = threadIdx.x, i = blockIdx.x * 1024 + t;
    int v = (i < NNODE) ? g_deg[i] : 0;
    sh[t] = v; __syncthreads();
    for (int o = 1; o < 1024; o <<= 1) {
        int add = (t >= o) ? sh[t - o] : 0;
        __syncthreads(); sh[t] += add; __syncthreads();
    }
    if (i < NNODE) g_off[i] = sh[t] - v;
    if (t == 1023) g_blocksum[blockIdx.x] = sh[t];
}

__global__ void __launch_bounds__(128) scan2_kernel() {
    __shared__ int sh[128];
    int t = threadIdx.x;
    int v = (t < NBLK_SCAN) ? g_blocksum[t] : 0;
    sh[t] = v; __syncthreads();
    for (int o = 1; o < 128; o <<= 1) {
        int add = (t >= o) ? sh[t - o] : 0;
        __syncthreads(); sh[t] += add; __syncthreads();
    }
    g_blocksum[t] = sh[t] - v;
}

__global__ void scan3_kernel() {
    int i = blockIdx.x * blockDim.x + threadIdx.x;
    if (i < NNODE) { g_off[i] += g_blocksum[i >> 10]; g_cur[i] = 0; }
}

__global__ void fill_kernel(const int* __restrict__ ei) {
    int e = blockIdx.x * blockDim.x + threadIdx.x;
    if (e >= EPLUS) return;
    int s, d;
    if (e < NEDGE) { s = ei[e]; d = ei[NEDGE + e]; } else { s = e - NEDGE; d = s; }
    int pos = g_off[d] + atomicAdd(&g_cur[d], 1);
    g_srcs[pos] = s;
}

// ---------------- GEMM: Y = f(X)[n,128] @ W[128,NCOL], 64-row tiles ----------
// threads = 2*NCOL; thread computes 8 rows x 4 cols. Also emits fp16 copy.
#define XPAD 68
template <int NCOL, bool PRERELU>
__global__ void __launch_bounds__(2 * NCOL) gemm_rows(
    const float* __restrict__ X, const float* __restrict__ W,
    const float* __restrict__ prebias, float* __restrict__ Y,
    __half* __restrict__ Yh, int n)
{
    extern __shared__ float sm[];
    float* sW  = sm;                  // 128 * NCOL
    float* sXT = sm + 128 * NCOL;     // 128 * XPAD (transposed, padded)
    const int T = 2 * NCOL;
    const int t = threadIdx.x;
    const int row0 = blockIdx.x * 64;

    for (int i = t; i < 128 * NCOL; i += T) sW[i] = W[i];

    // load X tile transposed: sXT[k*XPAD + r]
    for (int idx4 = t; idx4 < 64 * 32; idx4 += T) {
        int r = idx4 >> 5, c4 = idx4 & 31;
        int gr = row0 + r;
        float4 v = make_float4(0.f, 0.f, 0.f, 0.f);
        if (gr < n) v = *(const float4*)&X[gr * 128 + c4 * 4];
        if (PRERELU) {
            v.x = fmaxf(v.x + prebias[c4 * 4 + 0], 0.f);
            v.y = fmaxf(v.y + prebias[c4 * 4 + 1], 0.f);
            v.z = fmaxf(v.z + prebias[c4 * 4 + 2], 0.f);
            v.w = fmaxf(v.w + prebias[c4 * 4 + 3], 0.f);
        }
        sXT[(c4 * 4 + 0) * XPAD + r] = v.x;
        sXT[(c4 * 4 + 1) * XPAD + r] = v.y;
        sXT[(c4 * 4 + 2) * XPAD + r] = v.z;
        sXT[(c4 * 4 + 3) * XPAD + r] = v.w;
    }
    __syncthreads();

    const int col4 = (t % (NCOL / 4)) * 4;
    const int row8 = (t / (NCOL / 4)) * 8;

    float acc[8][4];
#pragma unroll
    for (int i = 0; i < 8; i++)
#pragma unroll
        for (int j = 0; j < 4; j++) acc[i][j] = 0.f;

#pragma unroll 4
    for (int k = 0; k < 128; k++) {
        float4 xa = *(const float4*)&sXT[k * XPAD + row8];
        float4 xb = *(const float4*)&sXT[k * XPAD + row8 + 4];
        float4 wv = *(const float4*)&sW[k * NCOL + col4];
        float xs[8] = {xa.x, xa.y, xa.z, xa.w, xb.x, xb.y, xb.z, xb.w};
#pragma unroll
        for (int i = 0; i < 8; i++) {
            acc[i][0] = fmaf(xs[i], wv.x, acc[i][0]);
            acc[i][1] = fmaf(xs[i], wv.y, acc[i][1]);
            acc[i][2] = fmaf(xs[i], wv.z, acc[i][2]);
            acc[i][3] = fmaf(xs[i], wv.w, acc[i][3]);
        }
    }

#pragma unroll
    for (int i = 0; i < 8; i++) {
        int gr = row0 + row8 + i;
        if (gr < n) {
            *(float4*)&Y[gr * NCOL + col4] =
                make_float4(acc[i][0], acc[i][1], acc[i][2], acc[i][3]);
            __half2 ha = __floats2half2_rn(acc[i][0], acc[i][1]);
            __half2 hb = __floats2half2_rn(acc[i][2], acc[i][3]);
            uint2 hu;
            hu.x = *(unsigned int*)&ha;
            hu.y = *(unsigned int*)&hb;
            *(uint2*)&Yh[gr * NCOL + col4] = hu;
        }
    }
}

// ---------------- attention-logit scores --------------------------------------
template <int NCOL>
__global__ void escore_kernel(const float* __restrict__ H,
                              const float* __restrict__ asrc,
                              const float* __restrict__ adst,
                              float* __restrict__ esrc,
                              float* __restrict__ edst, int n)
{
    int gw = (blockIdx.x * blockDim.x + threadIdx.x) >> 5;
    int lane = threadIdx.x & 31;
    if (gw >= n) return;

    if (NCOL == 128) {
        float4 h  = *(const float4*)&H[gw * 128 + lane * 4];
        float4 as = *(const float4*)&asrc[lane * 4];
        float4 ad = *(const float4*)&adst[lane * 4];
        float ps = h.x * as.x + h.y * as.y + h.z * as.z + h.w * as.w;
        float pd = h.x * ad.x + h.y * ad.y + h.z * ad.z + h.w * ad.w;
#pragma unroll
        for (int o = 8; o >= 1; o >>= 1) {
            ps += __shfl_xor_sync(FULLMASK, ps, o);
            pd += __shfl_xor_sync(FULLMASK, pd, o);
        }
        if ((lane & 15) == 0) {
            esrc[gw * 2 + (lane >> 4)] = ps;
            edst[gw * 2 + (lane >> 4)] = pd;
        }
    } else {
        float2 h  = *(const float2*)&H[gw * 64 + lane * 2];
        float2 as = *(const float2*)&asrc[lane * 2];
        float2 ad = *(const float2*)&adst[lane * 2];
        float ps = h.x * as.x + h.y * as.y;
        float pd = h.x * ad.x + h.y * ad.y;
#pragma unroll
        for (int o = 16; o >= 1; o >>= 1) {
            ps += __shfl_xor_sync(FULLMASK, ps, o);
            pd += __shfl_xor_sync(FULLMASK, pd, o);
        }
        if (lane == 0) { esrc[gw] = ps; edst[gw] = pd; }
    }
}

// ---------------- layer-1 gather: warp/node, half-warp/edge, fp16 msgs --------
__global__ void __launch_bounds__(256) gather1_kernel()
{
    int warp = (blockIdx.x * blockDim.x + threadIdx.x) >> 5;
    int lane = threadIdx.x & 31;
    if (warp >= NNODE) return;
    const int n = warp;
    const int base = g_off[n];
    const int m = g_deg[n];
    float2 ed = *(const float2*)&g_edst1[2 * n];

    const int hw = lane >> 4;          // which edge of the pair
    const int sub = lane & 15;
    const int head = sub >> 3;
    const int colbase = head * 64 + (sub & 7) * 8;   // 8 halfs per lane

    float acc[8];
#pragma unroll
    for (int i = 0; i < 8; i++) acc[i] = 0.f;
    float den0 = 0.f, den1 = 0.f;

    for (int k0 = 0; k0 < m; k0 += 32) {
        int kk = k0 + lane;
        int s = 0; float w0 = 0.f, w1 = 0.f;
        if (kk < m) {
            s = g_srcs[base + kk];
            float2 es = *(const float2*)&g_esrc1[2 * s];
            w0 = __expf(lrelu(es.x + ed.x));
            w1 = __expf(lrelu(es.y + ed.y));
        }
        den0 += w0; den1 += w1;
        int cnt = min(32, m - k0);
#pragma unroll 4
        for (int j = 0; j < cnt; j += 2) {
            int idx = j + hw;
            int   sj = __shfl_sync(FULLMASK, s,  idx);
            float wa = __shfl_sync(FULLMASK, w0, idx);
            float wb = __shfl_sync(FULLMASK, w1, idx);
            float wj = head ? wb : wa;
            if (idx < cnt) {
                uint4 hv = *(const uint4*)&g_h1h[sj * 128 + colbase];
                const __half2* hp = (const __half2*)&hv;
#pragma unroll
                for (int q = 0; q < 4; q++) {
                    float2 f = __half22float2(hp[q]);
                    acc[2 * q]     = fmaf(wj, f.x, acc[2 * q]);
                    acc[2 * q + 1] = fmaf(wj, f.y, acc[2 * q + 1]);
                }
            }
        }
    }
#pragma unroll
    for (int i = 0; i < 8; i++) acc[i] += __shfl_xor_sync(FULLMASK, acc[i], 16);
#pragma unroll
    for (int o = 16; o >= 1; o >>= 1) {
        den0 += __shfl_xor_sync(FULLMASK, den0, o);
        den1 += __shfl_xor_sync(FULLMASK, den1, o);
    }
    float inv = __fdividef(1.f, head ? den1 : den0);
    if (hw == 0) {
        *(float4*)&g_agg1[n * 128 + colbase] =
            make_float4(acc[0] * inv, acc[1] * inv, acc[2] * inv, acc[3] * inv);
        *(float4*)&g_agg1[n * 128 + colbase + 4] =
            make_float4(acc[4] * inv, acc[5] * inv, acc[6] * inv, acc[7] * inv);
    }
}

// ---------------- layer-2 gather + fused mean-pool ----------------------------
__global__ void __launch_bounds__(256) gather2_kernel(const int* __restrict__ batch)
{
    int warp = (blockIdx.x * blockDim.x + threadIdx.x) >> 5;
    int lane = threadIdx.x & 31;
    if (warp >= NNODE) return;
    const int n = warp;
    const int base = g_off[n];
    const int m = g_deg[n];
    float ed = g_edst2[n];

    const int hw = lane >> 4;
    const int sub = lane & 15;
    const int colbase = sub * 4;    // 4 halfs per lane

    float acc[4] = {0.f, 0.f, 0.f, 0.f};
    float den = 0.f;

    for (int k0 = 0; k0 < m; k0 += 32) {
        int kk = k0 + lane;
        int s = 0; float w = 0.f;
        if (kk < m) {
            s = g_srcs[base + kk];
            w = __expf(lrelu(g_esrc2[s] + ed));
        }
        den += w;
        int cnt = min(32, m - k0);
#pragma unroll 4
        for (int j = 0; j < cnt; j += 2) {
            int idx = j + hw;
            int   sj = __shfl_sync(FULLMASK, s, idx);
            float wj = __shfl_sync(FULLMASK, w, idx);
            if (idx < cnt) {
                uint2 hv = *(const uint2*)&g_h2h[sj * 64 + colbase];
                const __half2* hp = (const __half2*)&hv;
                float2 f0 = __half22float2(hp[0]);
                float2 f1 = __half22float2(hp[1]);
                acc[0] = fmaf(wj, f0.x, acc[0]);
                acc[1] = fmaf(wj, f0.y, acc[1]);
                acc[2] = fmaf(wj, f1.x, acc[2]);
                acc[3] = fmaf(wj, f1.y, acc[3]);
            }
        }
    }
#pragma unroll
    for (int i = 0; i < 4; i++) acc[i] += __shfl_xor_sync(FULLMASK, acc[i], 16);
#pragma unroll
    for (int o = 16; o >= 1; o >>= 1)
        den += __shfl_xor_sync(FULLMASK, den, o);
    float inv = __fdividef(1.f, den);
    if (hw == 0) {
        int g = batch[n];
        red_add_v2(&g_pool[g * 64 + colbase],     acc[0] * inv, acc[1] * inv);
        red_add_v2(&g_pool[g * 64 + colbase + 2], acc[2] * inv, acc[3] * inv);
    }
}

// ---------------- decoder MLP --------------------------------------------------
__global__ void __launch_bounds__(256) mlp_kernel(
    const int* __restrict__ batch,
    const float* __restrict__ b2,
    const float* __restrict__ dw1, const float* __restrict__ db1,
    const float* __restrict__ dw2, const float* __restrict__ db2,
    float* __restrict__ out)
{
    __shared__ float sp[64 * 64];
    __shared__ float sz[64 * 64];
    __shared__ float scnt[64];
    int t = threadIdx.x;

    if (t < 65) {
        int lo = 0, hi = NNODE;
        while (lo < hi) { int mid = (lo + hi) >> 1; if (batch[mid] < t) lo = mid + 1; else hi = mid; }
        sz[t] = (float)lo;
    }
    __syncthreads();
    if (t < 64) scnt[t] = fmaxf(sz[t + 1] - sz[t], 1.f);
    __syncthreads();

    for (int i = t; i < 4096; i += 256) {
        int g = i >> 6, c = i & 63;
        sp[i] = g_pool[i] / scnt[g] + b2[c];
    }
    __syncthreads();
    int j = t & 63, gq = t >> 6;
    for (int g = gq; g < 64; g += 4) {
        float a = db1[j];
#pragma unroll 8
        for (int c = 0; c < 64; c++) a = fmaf(sp[g * 64 + c], dw1[c * 64 + j], a);
        sz[g * 64 + j] = fmaxf(a, 0.f);
    }
    __syncthreads();
    for (int i = t; i < 64 * 16; i += 256) {
        int g = i >> 4, o = i & 15;
        float a = db2[o];
#pragma unroll 8
        for (int jj = 0; jj < 64; jj++) a = fmaf(sz[g * 64 + jj], dw2[jj * 16 + o], a);
        out[i] = a;
    }
}

// ---------------- launch --------------------------------------------------------
extern "C" void kernel_launch(void* const* d_in, const int* in_sizes, int n_in,
                              void* d_out, int out_size)
{
    const float* x    = (const float*)d_in[0];
    const int*   ei   = (const int*)  d_in[1];
    const int*   batch= (const int*)  d_in[2];
    const float* W1   = (const float*)d_in[3];
    const float* as1  = (const float*)d_in[4];
    const float* ad1  = (const float*)d_in[5];
    const float* b1   = (const float*)d_in[6];
    const float* W2   = (const float*)d_in[7];
    const float* as2  = (const float*)d_in[8];
    const float* ad2  = (const float*)d_in[9];
    const float* b2   = (const float*)d_in[10];
    const float* dw1  = (const float*)d_in[11];
    const float* db1  = (const float*)d_in[12];
    const float* dw2  = (const float*)d_in[13];
    const float* db2  = (const float*)d_in[14];
    float* out = (float*)d_out;

    float *h1p, *agg1p, *h2p, *es1p, *ed1p, *es2p, *ed2p;
    __half *h1hp, *h2hp;
    cudaGetSymbolAddress((void**)&h1p,   g_h1);
    cudaGetSymbolAddress((void**)&agg1p, g_agg1);
    cudaGetSymbolAddress((void**)&h2p,   g_h2);
    cudaGetSymbolAddress((void**)&h1hp,  g_h1h);
    cudaGetSymbolAddress((void**)&h2hp,  g_h2h);
    cudaGetSymbolAddress((void**)&es1p,  g_esrc1);
    cudaGetSymbolAddress((void**)&ed1p,  g_edst1);
    cudaGetSymbolAddress((void**)&es2p,  g_esrc2);
    cudaGetSymbolAddress((void**)&ed2p,  g_edst2);

    const int smem1 = (128 * 128 + 128 * XPAD) * (int)sizeof(float);  // ~100 KB
    const int smem2 = (128 * 64  + 128 * XPAD) * (int)sizeof(float);  // ~66 KB
    cudaFuncSetAttribute(gemm_rows<128, false>,
                         cudaFuncAttributeMaxDynamicSharedMemorySize, smem1);
    cudaFuncSetAttribute(gemm_rows<64, true>,
                         cudaFuncAttributeMaxDynamicSharedMemorySize, smem2);

    const int nblk64     = (NNODE + 63) / 64;
    const int node_blk   = (NNODE + 255) / 256;
    const int warp_blocks= (NNODE * 32 + 255) / 256;
    const int edge_blocks= (NEDGE + 255) / 256;
    const int eplus_blocks = (EPLUS + 255) / 256;
    const int gath_blocks  = (NNODE * 32 + 255) / 256;

    // ----- CSR build -----
    init_kernel<<<node_blk, 256>>>();
    deg_count_kernel<<<edge_blocks, 256>>>(ei);
    scan1_kernel<<<NBLK_SCAN, 1024>>>();
    scan2_kernel<<<1, 128>>>();
    scan3_kernel<<<node_blk, 256>>>();
    fill_kernel<<<eplus_blocks, 256>>>(ei);

    // ----- layer 1 -----
    gemm_rows<128, false><<<nblk64, 256, smem1>>>(x, W1, nullptr, h1p, h1hp, NNODE);
    escore_kernel<128><<<warp_blocks, 256>>>(h1p, as1, ad1, es1p, ed1p, NNODE);
    gather1_kernel<<<gath_blocks, 256>>>();

    // ----- layer 2 -----
    gemm_rows<64, true><<<nblk64, 128, smem2>>>(agg1p, W2, b1, h2p, h2hp, NNODE);
    escore_kernel<64><<<warp_blocks, 256>>>(h2p, as2, ad2, es2p, ed2p, NNODE);
    gather2_kernel<<<gath_blocks, 256>>>(batch);

    // ----- decoder -----
    mlp_kernel<<<1, 256>>>(batch, b2, dw1, db1, dw2, db2, out);
}

// round 4
// speedup vs baseline: 1.9059x; 1.2902x over previous
#include <cuda_runtime.h>
#include <cuda_fp16.h>

#define NNODE  100000
#define NEDGE  1600000
#define EPLUS  (NEDGE + NNODE)
#define GBATCH 64
#define NBLK_SCAN 98
#define FULLMASK 0xffffffffu

// ---------------- scratch ----------------------------------------------------
__device__ float  g_agg1[NNODE * 128];
__device__ __half g_h1h [NNODE * 128];
__device__ __half g_h2h [NNODE * 64];
__device__ float  g_esrc1[NNODE * 2];
__device__ float  g_edst1[NNODE * 2];
__device__ float  g_esrc2[NNODE];
__device__ float  g_edst2[NNODE];
__device__ float  g_pool[GBATCH * 64];
__device__ int    g_deg [NNODE];
__device__ int    g_off [NNODE];
__device__ int    g_cur [NNODE];
__device__ int    g_srcs[EPLUS];
__device__ int    g_blocksum[128];

// ---------------- helpers ----------------------------------------------------
__device__ __forceinline__ float lrelu(float v) { return v > 0.f ? v : 0.2f * v; }

__device__ __forceinline__ void red_add_v2(float* p, float a, float b) {
    asm volatile("red.global.add.v2.f32 [%0], {%1,%2};"
                 :: "l"(p), "f"(a), "f"(b) : "memory");
}

// ---------------- CSR build ---------------------------------------------------
__global__ void init_kernel() {
    int i = blockIdx.x * blockDim.x + threadIdx.x;
    if (i < NNODE) g_deg[i] = 1;
    if (i < GBATCH * 64) g_pool[i] = 0.f;
}

__global__ void deg_count_kernel(const int* __restrict__ ei) {
    int e = blockIdx.x * blockDim.x + threadIdx.x;
    if (e < NEDGE) atomicAdd(&g_deg[ei[NEDGE + e]], 1);
}

__global__ void __launch_bounds__(1024) scan1_kernel() {
    __shared__ int sh[1024];
    int t = threadIdx.x, i = blockIdx.x * 1024 + t;
    int v = (i < NNODE) ? g_deg[i] : 0;
    sh[t] = v; __syncthreads();
    for (int o = 1; o < 1024; o <<= 1) {
        int add = (t >= o) ? sh[t - o] : 0;
        __syncthreads(); sh[t] += add; __syncthreads();
    }
    if (i < NNODE) g_off[i] = sh[t] - v;
    if (t == 1023) g_blocksum[blockIdx.x] = sh[t];
}

__global__ void __launch_bounds__(128) scan2_kernel() {
    __shared__ int sh[128];
    int t = threadIdx.x;
    int v = (t < NBLK_SCAN) ? g_blocksum[t] : 0;
    sh[t] = v; __syncthreads();
    for (int o = 1; o < 128; o <<= 1) {
        int add = (t >= o) ? sh[t - o] : 0;
        __syncthreads(); sh[t] += add; __syncthreads();
    }
    g_blocksum[t] = sh[t] - v;
}

__global__ void scan3_kernel() {
    int i = blockIdx.x * blockDim.x + threadIdx.x;
    if (i < NNODE) { g_off[i] += g_blocksum[i >> 10]; g_cur[i] = 0; }
}

__global__ void fill_kernel(const int* __restrict__ ei) {
    int e = blockIdx.x * blockDim.x + threadIdx.x;
    if (e >= EPLUS) return;
    int s, d;
    if (e < NEDGE) { s = ei[e]; d = ei[NEDGE + e]; } else { s = e - NEDGE; d = s; }
    int pos = g_off[d] + atomicAdd(&g_cur[d], 1);
    g_srcs[pos] = s;
}

// ---------------- GEMM + fused escore: Yh = f(X)@W (fp16), e = h.a ------------
// threads = 2*NCOL; thread computes 8 rows x 4 cols.
#define XPAD 68
template <int NCOL, bool PRERELU>
__global__ void __launch_bounds__(2 * NCOL) gemm_rows(
    const float* __restrict__ X, const float* __restrict__ W,
    const float* __restrict__ prebias,
    const float* __restrict__ avsrc, const float* __restrict__ avdst,
    __half* __restrict__ Yh,
    float* __restrict__ esrc, float* __restrict__ edst, int n)
{
    extern __shared__ float sm[];
    float* sW  = sm;                  // 128 * NCOL
    float* sXT = sm + 128 * NCOL;     // 128 * XPAD
    const int T = 2 * NCOL;
    const int t = threadIdx.x;
    const int lane = t & 31;
    const int row0 = blockIdx.x * 64;

    for (int i = t; i < 128 * NCOL; i += T) sW[i] = W[i];

    for (int idx4 = t; idx4 < 64 * 32; idx4 += T) {
        int r = idx4 >> 5, c4 = idx4 & 31;
        int gr = row0 + r;
        float4 v = make_float4(0.f, 0.f, 0.f, 0.f);
        if (gr < n) v = *(const float4*)&X[gr * 128 + c4 * 4];
        if (PRERELU) {
            v.x = fmaxf(v.x + prebias[c4 * 4 + 0], 0.f);
            v.y = fmaxf(v.y + prebias[c4 * 4 + 1], 0.f);
            v.z = fmaxf(v.z + prebias[c4 * 4 + 2], 0.f);
            v.w = fmaxf(v.w + prebias[c4 * 4 + 3], 0.f);
        }
        sXT[(c4 * 4 + 0) * XPAD + r] = v.x;
        sXT[(c4 * 4 + 1) * XPAD + r] = v.y;
        sXT[(c4 * 4 + 2) * XPAD + r] = v.z;
        sXT[(c4 * 4 + 3) * XPAD + r] = v.w;
    }
    __syncthreads();

    const int col4 = (t % (NCOL / 4)) * 4;
    const int row8 = (t / (NCOL / 4)) * 8;

    float acc[8][4];
#pragma unroll
    for (int i = 0; i < 8; i++)
#pragma unroll
        for (int j = 0; j < 4; j++) acc[i][j] = 0.f;

#pragma unroll 4
    for (int k = 0; k < 128; k++) {
        float4 xa = *(const float4*)&sXT[k * XPAD + row8];
        float4 xb = *(const float4*)&sXT[k * XPAD + row8 + 4];
        float4 wv = *(const float4*)&sW[k * NCOL + col4];
        float xs[8] = {xa.x, xa.y, xa.z, xa.w, xb.x, xb.y, xb.z, xb.w};
#pragma unroll
        for (int i = 0; i < 8; i++) {
            acc[i][0] = fmaf(xs[i], wv.x, acc[i][0]);
            acc[i][1] = fmaf(xs[i], wv.y, acc[i][1]);
            acc[i][2] = fmaf(xs[i], wv.z, acc[i][2]);
            acc[i][3] = fmaf(xs[i], wv.w, acc[i][3]);
        }
    }

    // ---- store fp16 h ----
#pragma unroll
    for (int i = 0; i < 8; i++) {
        int gr = row0 + row8 + i;
        if (gr < n) {
            __half2 ha = __floats2half2_rn(acc[i][0], acc[i][1]);
            __half2 hb = __floats2half2_rn(acc[i][2], acc[i][3]);
            uint2 hu;
            hu.x = *(unsigned int*)&ha;
            hu.y = *(unsigned int*)&hb;
            *(uint2*)&Yh[gr * NCOL + col4] = hu;
        }
    }

    // ---- fused escore: reduce acc . a over the 16-lane column halves ----
    float4 as = *(const float4*)&avsrc[col4];
    float4 ad = *(const float4*)&avdst[col4];
#pragma unroll
    for (int i = 0; i < 8; i++) {
        float ps = acc[i][0] * as.x + acc[i][1] * as.y + acc[i][2] * as.z + acc[i][3] * as.w;
        float pd = acc[i][0] * ad.x + acc[i][1] * ad.y + acc[i][2] * ad.z + acc[i][3] * ad.w;
#pragma unroll
        for (int o = 8; o >= 1; o >>= 1) {
            ps += __shfl_xor_sync(FULLMASK, ps, o);
            pd += __shfl_xor_sync(FULLMASK, pd, o);
        }
        int gr = row0 + row8 + i;
        if ((lane & 15) == 0 && gr < n) {
            if (NCOL == 128) {               // 2 heads: lane 0 -> head0, lane 16 -> head1
                int head = lane >> 4;
                esrc[gr * 2 + head] = ps;
                edst[gr * 2 + head] = pd;
            } else {                          // 1 head; both 16-lane halves own distinct rows
                esrc[gr] = ps;
                edst[gr] = pd;
            }
        }
    }
}

// ---------------- layer-1 gather: warp/node, smem-staged weights --------------
__global__ void __launch_bounds__(256) gather1_kernel()
{
    __shared__ int   ss[8][32];
    __shared__ float sw[8][2][32];
    const int wid = threadIdx.x >> 5, lane = threadIdx.x & 31;
    const int n = blockIdx.x * 8 + wid;
    if (n >= NNODE) return;
    const int base = g_off[n];
    const int m = g_deg[n];
    const float2 ed = *(const float2*)&g_edst1[2 * n];
    const int head = lane >> 4;
    const int col = lane * 4;                // lane owns 4 cols of 128

    float a0 = 0.f, a1 = 0.f, a2 = 0.f, a3 = 0.f;
    float den0 = 0.f, den1 = 0.f;

    for (int k0 = 0; k0 < m; k0 += 32) {
        int kk = k0 + lane;
        int s = 0; float w0 = 0.f, w1 = 0.f;
        if (kk < m) {
            s = g_srcs[base + kk];
            float2 es = *(const float2*)&g_esrc1[2 * s];
            w0 = __expf(lrelu(es.x + ed.x));
            w1 = __expf(lrelu(es.y + ed.y));
        }
        den0 += w0; den1 += w1;
        ss[wid][lane] = s;
        sw[wid][0][lane] = w0;
        sw[wid][1][lane] = w1;
        __syncwarp();
        int cnt = min(32, m - k0);
#pragma unroll 4
        for (int j = 0; j < cnt; j++) {
            int   sj = ss[wid][j];
            float wj = sw[wid][head][j];
            uint2 hv = *(const uint2*)&g_h1h[sj * 128 + col];
            const __half2* hp = (const __half2*)&hv;
            float2 f0 = __half22float2(hp[0]);
            float2 f1 = __half22float2(hp[1]);
            a0 = fmaf(wj, f0.x, a0);
            a1 = fmaf(wj, f0.y, a1);
            a2 = fmaf(wj, f1.x, a2);
            a3 = fmaf(wj, f1.y, a3);
        }
        __syncwarp();
    }
#pragma unroll
    for (int o = 16; o >= 1; o >>= 1) {
        den0 += __shfl_xor_sync(FULLMASK, den0, o);
        den1 += __shfl_xor_sync(FULLMASK, den1, o);
    }
    float inv = __fdividef(1.f, head ? den1 : den0);
    *(float4*)&g_agg1[n * 128 + col] =
        make_float4(a0 * inv, a1 * inv, a2 * inv, a3 * inv);
}

// ---------------- layer-2 gather + fused mean-pool ----------------------------
__global__ void __launch_bounds__(256) gather2_kernel(const int* __restrict__ batch)
{
    __shared__ int   ss[8][32];
    __shared__ float sw[8][32];
    const int wid = threadIdx.x >> 5, lane = threadIdx.x & 31;
    const int n = blockIdx.x * 8 + wid;
    if (n >= NNODE) return;
    const int base = g_off[n];
    const int m = g_deg[n];
    const float ed = g_edst2[n];
    const int col = lane * 2;                // lane owns 2 cols of 64

    float a0 = 0.f, a1 = 0.f;
    float den = 0.f;

    for (int k0 = 0; k0 < m; k0 += 32) {
        int kk = k0 + lane;
        int s = 0; float w = 0.f;
        if (kk < m) {
            s = g_srcs[base + kk];
            w = __expf(lrelu(g_esrc2[s] + ed));
        }
        den += w;
        ss[wid][lane] = s;
        sw[wid][lane] = w;
        __syncwarp();
        int cnt = min(32, m - k0);
#pragma unroll 4
        for (int j = 0; j < cnt; j++) {
            int   sj = ss[wid][j];
            float wj = sw[wid][j];
            unsigned int hv = *(const unsigned int*)&g_h2h[sj * 64 + col];
            float2 f = __half22float2(*(const __half2*)&hv);
            a0 = fmaf(wj, f.x, a0);
            a1 = fmaf(wj, f.y, a1);
        }
        __syncwarp();
    }
#pragma unroll
    for (int o = 16; o >= 1; o >>= 1)
        den += __shfl_xor_sync(FULLMASK, den, o);
    float inv = __fdividef(1.f, den);
    int g = batch[n];
    red_add_v2(&g_pool[g * 64 + col], a0 * inv, a1 * inv);
}

// ---------------- decoder MLP --------------------------------------------------
__global__ void __launch_bounds__(256) mlp_kernel(
    const int* __restrict__ batch,
    const float* __restrict__ b2,
    const float* __restrict__ dw1, const float* __restrict__ db1,
    const float* __restrict__ dw2, const float* __restrict__ db2,
    float* __restrict__ out)
{
    __shared__ float sp[64 * 64];
    __shared__ float sz[64 * 64];
    __shared__ float scnt[64];
    int t = threadIdx.x;

    if (t < 65) {
        int lo = 0, hi = NNODE;
        while (lo < hi) { int mid = (lo + hi) >> 1; if (batch[mid] < t) lo = mid + 1; else hi = mid; }
        sz[t] = (float)lo;
    }
    __syncthreads();
    if (t < 64) scnt[t] = fmaxf(sz[t + 1] - sz[t], 1.f);
    __syncthreads();

    for (int i = t; i < 4096; i += 256) {
        int g = i >> 6, c = i & 63;
        sp[i] = g_pool[i] / scnt[g] + b2[c];
    }
    __syncthreads();
    int j = t & 63, gq = t >> 6;
    for (int g = gq; g < 64; g += 4) {
        float a = db1[j];
#pragma unroll 8
        for (int c = 0; c < 64; c++) a = fmaf(sp[g * 64 + c], dw1[c * 64 + j], a);
        sz[g * 64 + j] = fmaxf(a, 0.f);
    }
    __syncthreads();
    for (int i = t; i < 64 * 16; i += 256) {
        int g = i >> 4, o = i & 15;
        float a = db2[o];
#pragma unroll 8
        for (int jj = 0; jj < 64; jj++) a = fmaf(sz[g * 64 + jj], dw2[jj * 16 + o], a);
        out[i] = a;
    }
}

// ---------------- launch --------------------------------------------------------
extern "C" void kernel_launch(void* const* d_in, const int* in_sizes, int n_in,
                              void* d_out, int out_size)
{
    const float* x    = (const float*)d_in[0];
    const int*   ei   = (const int*)  d_in[1];
    const int*   batch= (const int*)  d_in[2];
    const float* W1   = (const float*)d_in[3];
    const float* as1  = (const float*)d_in[4];
    const float* ad1  = (const float*)d_in[5];
    const float* b1   = (const float*)d_in[6];
    const float* W2   = (const float*)d_in[7];
    const float* as2  = (const float*)d_in[8];
    const float* ad2  = (const float*)d_in[9];
    const float* b2   = (const float*)d_in[10];
    const float* dw1  = (const float*)d_in[11];
    const float* db1  = (const float*)d_in[12];
    const float* dw2  = (const float*)d_in[13];
    const float* db2  = (const float*)d_in[14];
    float* out = (float*)d_out;

    float *agg1p, *es1p, *ed1p, *es2p, *ed2p;
    __half *h1hp, *h2hp;
    cudaGetSymbolAddress((void**)&agg1p, g_agg1);
    cudaGetSymbolAddress((void**)&h1hp,  g_h1h);
    cudaGetSymbolAddress((void**)&h2hp,  g_h2h);
    cudaGetSymbolAddress((void**)&es1p,  g_esrc1);
    cudaGetSymbolAddress((void**)&ed1p,  g_edst1);
    cudaGetSymbolAddress((void**)&es2p,  g_esrc2);
    cudaGetSymbolAddress((void**)&ed2p,  g_edst2);

    const int smem1 = (128 * 128 + 128 * XPAD) * (int)sizeof(float);
    const int smem2 = (128 * 64  + 128 * XPAD) * (int)sizeof(float);
    cudaFuncSetAttribute(gemm_rows<128, false>,
                         cudaFuncAttributeMaxDynamicSharedMemorySize, smem1);
    cudaFuncSetAttribute(gemm_rows<64, true>,
                         cudaFuncAttributeMaxDynamicSharedMemorySize, smem2);

    const int nblk64       = (NNODE + 63) / 64;
    const int node_blk     = (NNODE + 255) / 256;
    const int edge_blocks  = (NEDGE + 255) / 256;
    const int eplus_blocks = (EPLUS + 255) / 256;
    const int gath_blocks  = (NNODE + 7) / 8;

    // ----- CSR build interleaved with GEMM1 (gemm1 is the 4th launch -> profiled)
    init_kernel<<<node_blk, 256>>>();
    deg_count_kernel<<<edge_blocks, 256>>>(ei);
    scan1_kernel<<<NBLK_SCAN, 1024>>>();
    gemm_rows<128, false><<<nblk64, 256, smem1>>>(x, W1, nullptr, as1, ad1,
                                                  h1hp, es1p, ed1p, NNODE);
    scan2_kernel<<<1, 128>>>();
    scan3_kernel<<<node_blk, 256>>>();
    fill_kernel<<<eplus_blocks, 256>>>(ei);

    // ----- layer 1 gather -----
    gather1_kernel<<<gath_blocks, 256>>>();

    // ----- layer 2 -----
    gemm_rows<64, true><<<nblk64, 128, smem2>>>(agg1p, W2, b1, as2, ad2,
                                                h2hp, es2p, ed2p, NNODE);
    gather2_kernel<<<gath_blocks, 256>>>(batch);

    // ----- decoder -----
    mlp_kernel<<<1, 256>>>(batch, b2, dw1, db1, dw2, db2, out);
}

// round 5
// speedup vs baseline: 2.1207x; 1.1127x over previous
#include <cuda_runtime.h>
#include <cuda_fp16.h>
#include <stdint.h>

#define NNODE  100000
#define NEDGE  1600000
#define EPLUS  (NEDGE + NNODE)
#define GBATCH 64
#define NBLK_SCAN 98
#define FULLMASK 0xffffffffu

// ---------------- scratch ----------------------------------------------------
__device__ float  g_agg1[NNODE * 128];
__device__ __half g_h1h [NNODE * 128];
__device__ __half g_h2h [NNODE * 64];
__device__ float  g_esrc1[NNODE * 2];
__device__ float  g_edst1[NNODE * 2];
__device__ float  g_esrc2[NNODE];
__device__ float  g_edst2[NNODE];
__device__ float  g_pool[GBATCH * 64];
__device__ int    g_deg [NNODE];
__device__ int    g_off [NNODE];
__device__ int    g_cur [NNODE];
__device__ int    g_srcs[EPLUS];
__device__ int    g_blocksum[128];

// ---------------- helpers ----------------------------------------------------
__device__ __forceinline__ float lrelu(float v) { return v > 0.f ? v : 0.2f * v; }

__device__ __forceinline__ void red_add_v2(float* p, float a, float b) {
    asm volatile("red.global.add.v2.f32 [%0], {%1,%2};"
                 :: "l"(p), "f"(a), "f"(b) : "memory");
}

__device__ __forceinline__ uint32_t smem_u32(const void* p) {
    return (uint32_t)__cvta_generic_to_shared(p);
}

__device__ __forceinline__ void ldsm_x4(uint32_t* r, uint32_t addr) {
    asm volatile("ldmatrix.sync.aligned.m8n8.x4.shared.b16 {%0,%1,%2,%3}, [%4];"
                 : "=r"(r[0]), "=r"(r[1]), "=r"(r[2]), "=r"(r[3]) : "r"(addr));
}

__device__ __forceinline__ void ldsm_x4t(uint32_t* r, uint32_t addr) {
    asm volatile("ldmatrix.sync.aligned.m8n8.x4.trans.shared.b16 {%0,%1,%2,%3}, [%4];"
                 : "=r"(r[0]), "=r"(r[1]), "=r"(r[2]), "=r"(r[3]) : "r"(addr));
}

__device__ __forceinline__ void mma_16816(float* d, const uint32_t* a,
                                          uint32_t b0, uint32_t b1) {
    asm volatile(
        "mma.sync.aligned.m16n8k16.row.col.f32.f16.f16.f32 "
        "{%0,%1,%2,%3}, {%4,%5,%6,%7}, {%8,%9}, {%0,%1,%2,%3};"
        : "+f"(d[0]), "+f"(d[1]), "+f"(d[2]), "+f"(d[3])
        : "r"(a[0]), "r"(a[1]), "r"(a[2]), "r"(a[3]), "r"(b0), "r"(b1));
}

// ---------------- CSR build ---------------------------------------------------
__global__ void init_kernel() {
    int i = blockIdx.x * blockDim.x + threadIdx.x;
    if (i < NNODE) g_deg[i] = 1;
    if (i < GBATCH * 64) g_pool[i] = 0.f;
}

__global__ void deg_count_kernel(const int* __restrict__ ei) {
    int e = blockIdx.x * blockDim.x + threadIdx.x;
    if (e < NEDGE) atomicAdd(&g_deg[ei[NEDGE + e]], 1);
}

__global__ void __launch_bounds__(1024) scan1_kernel() {
    __shared__ int sh[1024];
    int t = threadIdx.x, i = blockIdx.x * 1024 + t;
    int v = (i < NNODE) ? g_deg[i] : 0;
    sh[t] = v; __syncthreads();
    for (int o = 1; o < 1024; o <<= 1) {
        int add = (t >= o) ? sh[t - o] : 0;
        __syncthreads(); sh[t] += add; __syncthreads();
    }
    if (i < NNODE) g_off[i] = sh[t] - v;
    if (t == 1023) g_blocksum[blockIdx.x] = sh[t];
}

__global__ void __launch_bounds__(128) scan2_kernel() {
    __shared__ int sh[128];
    int t = threadIdx.x;
    int v = (t < NBLK_SCAN) ? g_blocksum[t] : 0;
    sh[t] = v; __syncthreads();
    for (int o = 1; o < 128; o <<= 1) {
        int add = (t >= o) ? sh[t - o] : 0;
        __syncthreads(); sh[t] += add; __syncthreads();
    }
    g_blocksum[t] = sh[t] - v;
}

__global__ void scan3_kernel() {
    int i = blockIdx.x * blockDim.x + threadIdx.x;
    if (i < NNODE) { g_off[i] += g_blocksum[i >> 10]; g_cur[i] = 0; }
}

__global__ void fill_kernel(const int* __restrict__ ei) {
    int e = blockIdx.x * blockDim.x + threadIdx.x;
    if (e >= EPLUS) return;
    int s, d;
    if (e < NEDGE) { s = ei[e]; d = ei[NEDGE + e]; } else { s = e - NEDGE; d = s; }
    int pos = g_off[d] + atomicAdd(&g_cur[d], 1);
    g_srcs[pos] = s;
}

// ---------------- HMMA GEMM + fused escore -----------------------------------
// C[128 rows, NCOL] = f(X)[128,128] @ W[128,NCOL]; fp16 in, fp32 accum.
// NCOL=128: 256 thr (8 warps, 2m x 4n); NCOL=64: 128 thr (4 warps, 2m x 2n).
// Warp tile 64x32, mma m16n8k16, K=128 (8 k-steps).
template <int NCOL, bool PRERELU>
__global__ void __launch_bounds__(NCOL == 128 ? 256 : 128) gemm_mma(
    const float* __restrict__ X, const float* __restrict__ W,
    const float* __restrict__ prebias,
    const float* __restrict__ avsrc, const float* __restrict__ avdst,
    __half* __restrict__ Yh,
    float* __restrict__ esrc, float* __restrict__ edst, int n)
{
    constexpr int T  = (NCOL == 128) ? 256 : 128;
    constexpr int NW = NCOL / 32;       // warps along n
    constexpr int PX = 136;             // X smem pitch (halves)
    constexpr int PW = NCOL + 8;        // W smem pitch (halves)

    extern __shared__ char smraw[];
    __half* sX = (__half*)smraw;                    // 128 * PX
    __half* sW = sX + 128 * PX;                     // 128 * PW
    float*  ps = (float*)(sW + 128 * PW);           // 128 * NW
    float*  pd = ps + 128 * NW;                     // 128 * NW

    const int t = threadIdx.x;
    const int lane = t & 31, wid = t >> 5;
    const int row0 = blockIdx.x * 128;

    // ---- load W -> fp16 smem ----
#pragma unroll
    for (int i = t; i < 128 * NCOL / 4; i += T) {
        int k = i / (NCOL / 4), c4 = i % (NCOL / 4);
        float4 v = *(const float4*)&W[k * NCOL + c4 * 4];
        __half2 h0 = __floats2half2_rn(v.x, v.y);
        __half2 h1 = __floats2half2_rn(v.z, v.w);
        uint2 u;
        u.x = *(uint32_t*)&h0; u.y = *(uint32_t*)&h1;
        *(uint2*)&sW[k * PW + c4 * 4] = u;
    }
    // ---- load X (with optional relu(x+b)) -> fp16 smem ----
#pragma unroll
    for (int i = t; i < 128 * 32; i += T) {
        int r = i >> 5, c4 = i & 31;
        int gr = row0 + r;
        float4 v = make_float4(0.f, 0.f, 0.f, 0.f);
        if (gr < n) v = *(const float4*)&X[gr * 128 + c4 * 4];
        if (PRERELU) {
            float4 pb = *(const float4*)&prebias[c4 * 4];
            v.x = fmaxf(v.x + pb.x, 0.f);
            v.y = fmaxf(v.y + pb.y, 0.f);
            v.z = fmaxf(v.z + pb.z, 0.f);
            v.w = fmaxf(v.w + pb.w, 0.f);
        }
        __half2 h0 = __floats2half2_rn(v.x, v.y);
        __half2 h1 = __floats2half2_rn(v.z, v.w);
        uint2 u;
        u.x = *(uint32_t*)&h0; u.y = *(uint32_t*)&h1;
        *(uint2*)&sX[r * PX + c4 * 4] = u;
    }
    __syncthreads();

    const int warpM = wid & 1, warpN = wid >> 1;
    float d[4][4][4];
#pragma unroll
    for (int a = 0; a < 4; a++)
#pragma unroll
        for (int b = 0; b < 4; b++)
#pragma unroll
            for (int c = 0; c < 4; c++) d[a][b][c] = 0.f;

    // ldmatrix address components (same pattern for A and B)
    const int lrow = (lane & 7) + 8 * ((lane >> 3) & 1);  // 0..15
    const int loff = 8 * (lane >> 4);                     // 0 or 8
    const uint32_t aBase = smem_u32(sX);
    const uint32_t bBase = smem_u32(sW);

#pragma unroll
    for (int k = 0; k < 8; k++) {
        uint32_t a[4][4];
#pragma unroll
        for (int mt = 0; mt < 4; mt++)
            ldsm_x4(a[mt], aBase +
                ((warpM * 64 + mt * 16 + lrow) * PX + k * 16 + loff) * 2);
        uint32_t b[2][4];
#pragma unroll
        for (int p = 0; p < 2; p++)
            ldsm_x4t(b[p], bBase +
                ((k * 16 + lrow) * PW + warpN * 32 + p * 16 + loff) * 2);
#pragma unroll
        for (int mt = 0; mt < 4; mt++) {
#pragma unroll
            for (int p = 0; p < 2; p++) {
                mma_16816(d[mt][2 * p],     a[mt], b[p][0], b[p][1]);
                mma_16816(d[mt][2 * p + 1], a[mt], b[p][2], b[p][3]);
            }
        }
    }

    // ---- epilogue: fp16 store + escore partials ----
    const int tc = lane & 3, g = lane >> 2;
#pragma unroll
    for (int mt = 0; mt < 4; mt++) {
        int rl = warpM * 64 + mt * 16 + g;
        int rh = rl + 8;
        int gl = row0 + rl, gh = row0 + rh;
        float sl = 0.f, dl = 0.f, shp = 0.f, dh = 0.f;
#pragma unroll
        for (int nt = 0; nt < 4; nt++) {
            int col = warpN * 32 + nt * 8 + 2 * tc;
            float2 avs = *(const float2*)&avsrc[col];
            float2 avd = *(const float2*)&avdst[col];
            float c0 = d[mt][nt][0], c1 = d[mt][nt][1];
            float c2 = d[mt][nt][2], c3 = d[mt][nt][3];
            sl  += c0 * avs.x + c1 * avs.y;
            dl  += c0 * avd.x + c1 * avd.y;
            shp += c2 * avs.x + c3 * avs.y;
            dh  += c2 * avd.x + c3 * avd.y;
            if (gl < n) *(__half2*)&Yh[gl * NCOL + col] = __floats2half2_rn(c0, c1);
            if (gh < n) *(__half2*)&Yh[gh * NCOL + col] = __floats2half2_rn(c2, c3);
        }
#pragma unroll
        for (int o = 1; o <= 2; o <<= 1) {
            sl  += __shfl_xor_sync(FULLMASK, sl,  o);
            dl  += __shfl_xor_sync(FULLMASK, dl,  o);
            shp += __shfl_xor_sync(FULLMASK, shp, o);
            dh  += __shfl_xor_sync(FULLMASK, dh,  o);
        }
        if (tc == 0) {
            ps[rl * NW + warpN] = sl;  pd[rl * NW + warpN] = dl;
            ps[rh * NW + warpN] = shp; pd[rh * NW + warpN] = dh;
        }
    }
    __syncthreads();

    if (NCOL == 128) {
        if (t < 128) {
            int gr = row0 + t;
            if (gr < n) {
                esrc[gr * 2 + 0] = ps[t * 4 + 0] + ps[t * 4 + 1];
                esrc[gr * 2 + 1] = ps[t * 4 + 2] + ps[t * 4 + 3];
            }
        } else {
            int r = t - 128, gr = row0 + r;
            if (gr < n) {
                edst[gr * 2 + 0] = pd[r * 4 + 0] + pd[r * 4 + 1];
                edst[gr * 2 + 1] = pd[r * 4 + 2] + pd[r * 4 + 3];
            }
        }
    } else {
        int gr = row0 + t;
        if (gr < n) {
            esrc[gr] = ps[t * 2 + 0] + ps[t * 2 + 1];
            edst[gr] = pd[t * 2 + 0] + pd[t * 2 + 1];
        }
    }
}

// ---------------- layer-1 gather: warp/node, 2 edges per iter -----------------
__global__ void __launch_bounds__(256) gather1_kernel()
{
    __shared__ uint2 pk[2][8][32];   // [head][warp][edge-in-batch] = {src, wbits}
    const int wid = threadIdx.x >> 5, lane = threadIdx.x & 31;
    const int n = blockIdx.x * 8 + wid;
    if (n >= NNODE) return;
    const int base = g_off[n];
    const int m = g_deg[n];
    const float2 ed = *(const float2*)&g_edst1[2 * n];
    const int half = lane >> 4;          // edge parity within pair
    const int sub  = lane & 15;          // owns 8 cols: sub*8
    const int head = sub >> 3;           // cols<64 -> head0

    float a0 = 0.f, a1 = 0.f, a2 = 0.f, a3 = 0.f;
    float a4 = 0.f, a5 = 0.f, a6 = 0.f, a7 = 0.f;
    float den0 = 0.f, den1 = 0.f;

    for (int k0 = 0; k0 < m; k0 += 32) {
        int kk = k0 + lane;
        int s = 0; float w0 = 0.f, w1 = 0.f;
        if (kk < m) {
            s = g_srcs[base + kk];
            float2 es = *(const float2*)&g_esrc1[2 * s];
            w0 = __expf(lrelu(es.x + ed.x));
            w1 = __expf(lrelu(es.y + ed.y));
        }
        den0 += w0; den1 += w1;
        pk[0][wid][lane] = make_uint2((unsigned)s, __float_as_uint(w0));
        pk[1][wid][lane] = make_uint2((unsigned)s, __float_as_uint(w1));
        __syncwarp();
        int cnt = min(32, m - k0);
#pragma unroll 4
        for (int j = 0; j < cnt; j += 2) {
            int idx = j + half;
            uint2 e = pk[head][wid][idx];
            if (idx < cnt) {
                float wj = __uint_as_float(e.y);
                uint4 hv = *(const uint4*)&g_h1h[e.x * 128 + sub * 8];
                const __half2* hp = (const __half2*)&hv;
                float2 f0 = __half22float2(hp[0]);
                float2 f1 = __half22float2(hp[1]);
                float2 f2 = __half22float2(hp[2]);
                float2 f3 = __half22float2(hp[3]);
                a0 = fmaf(wj, f0.x, a0); a1 = fmaf(wj, f0.y, a1);
                a2 = fmaf(wj, f1.x, a2); a3 = fmaf(wj, f1.y, a3);
                a4 = fmaf(wj, f2.x, a4); a5 = fmaf(wj, f2.y, a5);
                a6 = fmaf(wj, f3.x, a6); a7 = fmaf(wj, f3.y, a7);
            }
        }
        __syncwarp();
    }
    // combine the two edge-parity halves (same cols, different edges)
    a0 += __shfl_xor_sync(FULLMASK, a0, 16);
    a1 += __shfl_xor_sync(FULLMASK, a1, 16);
    a2 += __shfl_xor_sync(FULLMASK, a2, 16);
    a3 += __shfl_xor_sync(FULLMASK, a3, 16);
    a4 += __shfl_xor_sync(FULLMASK, a4, 16);
    a5 += __shfl_xor_sync(FULLMASK, a5, 16);
    a6 += __shfl_xor_sync(FULLMASK, a6, 16);
    a7 += __shfl_xor_sync(FULLMASK, a7, 16);
#pragma unroll
    for (int o = 16; o >= 1; o >>= 1) {
        den0 += __shfl_xor_sync(FULLMASK, den0, o);
        den1 += __shfl_xor_sync(FULLMASK, den1, o);
    }
    float inv = __fdividef(1.f, head ? den1 : den0);
    if (half == 0) {
        *(float4*)&g_agg1[n * 128 + sub * 8] =
            make_float4(a0 * inv, a1 * inv, a2 * inv, a3 * inv);
        *(float4*)&g_agg1[n * 128 + sub * 8 + 4] =
            make_float4(a4 * inv, a5 * inv, a6 * inv, a7 * inv);
    }
}

// ---------------- layer-2 gather + fused mean-pool ----------------------------
__global__ void __launch_bounds__(256) gather2_kernel(const int* __restrict__ batch)
{
    __shared__ uint2 pk[8][32];
    const int wid = threadIdx.x >> 5, lane = threadIdx.x & 31;
    const int n = blockIdx.x * 8 + wid;
    if (n >= NNODE) return;
    const int base = g_off[n];
    const int m = g_deg[n];
    const float ed = g_edst2[n];
    const int half = lane >> 4;
    const int sub  = lane & 15;          // owns 4 cols: sub*4

    float a0 = 0.f, a1 = 0.f, a2 = 0.f, a3 = 0.f;
    float den = 0.f;

    for (int k0 = 0; k0 < m; k0 += 32) {
        int kk = k0 + lane;
        int s = 0; float w = 0.f;
        if (kk < m) {
            s = g_srcs[base + kk];
            w = __expf(lrelu(g_esrc2[s] + ed));
        }
        den += w;
        pk[wid][lane] = make_uint2((unsigned)s, __float_as_uint(w));
        __syncwarp();
        int cnt = min(32, m - k0);
#pragma unroll 4
        for (int j = 0; j < cnt; j += 2) {
            int idx = j + half;
            uint2 e = pk[wid][idx];
            if (idx < cnt) {
                float wj = __uint_as_float(e.y);
                uint2 hv = *(const uint2*)&g_h2h[e.x * 64 + sub * 4];
                const __half2* hp = (const __half2*)&hv;
                float2 f0 = __half22float2(hp[0]);
                float2 f1 = __half22float2(hp[1]);
                a0 = fmaf(wj, f0.x, a0); a1 = fmaf(wj, f0.y, a1);
                a2 = fmaf(wj, f1.x, a2); a3 = fmaf(wj, f1.y, a3);
            }
        }
        __syncwarp();
    }
    a0 += __shfl_xor_sync(FULLMASK, a0, 16);
    a1 += __shfl_xor_sync(FULLMASK, a1, 16);
    a2 += __shfl_xor_sync(FULLMASK, a2, 16);
    a3 += __shfl_xor_sync(FULLMASK, a3, 16);
#pragma unroll
    for (int o = 16; o >= 1; o >>= 1)
        den += __shfl_xor_sync(FULLMASK, den, o);
    float inv = __fdividef(1.f, den);
    if (half == 0) {
        int g = batch[n];
        red_add_v2(&g_pool[g * 64 + sub * 4],     a0 * inv, a1 * inv);
        red_add_v2(&g_pool[g * 64 + sub * 4 + 2], a2 * inv, a3 * inv);
    }
}

// ---------------- decoder MLP --------------------------------------------------
__global__ void __launch_bounds__(256) mlp_kernel(
    const int* __restrict__ batch,
    const float* __restrict__ b2,
    const float* __restrict__ dw1, const float* __restrict__ db1,
    const float* __restrict__ dw2, const float* __restrict__ db2,
    float* __restrict__ out)
{
    __shared__ float sp[64 * 64];
    __shared__ float sz[64 * 64];
    __shared__ float scnt[64];
    int t = threadIdx.x;

    if (t < 65) {
        int lo = 0, hi = NNODE;
        while (lo < hi) { int mid = (lo + hi) >> 1; if (batch[mid] < t) lo = mid + 1; else hi = mid; }
        sz[t] = (float)lo;
    }
    __syncthreads();
    if (t < 64) scnt[t] = fmaxf(sz[t + 1] - sz[t], 1.f);
    __syncthreads();

    for (int i = t; i < 4096; i += 256) {
        int g = i >> 6, c = i & 63;
        sp[i] = g_pool[i] / scnt[g] + b2[c];
    }
    __syncthreads();
    int j = t & 63, gq = t >> 6;
    for (int g = gq; g < 64; g += 4) {
        float a = db1[j];
#pragma unroll 8
        for (int c = 0; c < 64; c++) a = fmaf(sp[g * 64 + c], dw1[c * 64 + j], a);
        sz[g * 64 + j] = fmaxf(a, 0.f);
    }
    __syncthreads();
    for (int i = t; i < 64 * 16; i += 256) {
        int g = i >> 4, o = i & 15;
        float a = db2[o];
#pragma unroll 8
        for (int jj = 0; jj < 64; jj++) a = fmaf(sz[g * 64 + jj], dw2[jj * 16 + o], a);
        out[i] = a;
    }
}

// ---------------- launch --------------------------------------------------------
extern "C" void kernel_launch(void* const* d_in, const int* in_sizes, int n_in,
                              void* d_out, int out_size)
{
    const float* x    = (const float*)d_in[0];
    const int*   ei   = (const int*)  d_in[1];
    const int*   batch= (const int*)  d_in[2];
    const float* W1   = (const float*)d_in[3];
    const float* as1  = (const float*)d_in[4];
    const float* ad1  = (const float*)d_in[5];
    const float* b1   = (const float*)d_in[6];
    const float* W2   = (const float*)d_in[7];
    const float* as2  = (const float*)d_in[8];
    const float* ad2  = (const float*)d_in[9];
    const float* b2   = (const float*)d_in[10];
    const float* dw1  = (const float*)d_in[11];
    const float* db1  = (const float*)d_in[12];
    const float* dw2  = (const float*)d_in[13];
    const float* db2  = (const float*)d_in[14];
    float* out = (float*)d_out;

    float *agg1p, *es1p, *ed1p, *es2p, *ed2p;
    __half *h1hp, *h2hp;
    cudaGetSymbolAddress((void**)&agg1p, g_agg1);
    cudaGetSymbolAddress((void**)&h1hp,  g_h1h);
    cudaGetSymbolAddress((void**)&h2hp,  g_h2h);
    cudaGetSymbolAddress((void**)&es1p,  g_esrc1);
    cudaGetSymbolAddress((void**)&ed1p,  g_edst1);
    cudaGetSymbolAddress((void**)&es2p,  g_esrc2);
    cudaGetSymbolAddress((void**)&ed2p,  g_edst2);

    // dynamic smem: X(128*136) + W(128*(NCOL+8)) halves + 2*128*NW floats
    const int smem1 = (128 * 136 + 128 * 136) * 2 + 2 * 128 * 4 * 4;  // 73728
    const int smem2 = (128 * 136 + 128 * 72)  * 2 + 2 * 128 * 2 * 4;  // 55296
    cudaFuncSetAttribute(gemm_mma<128, false>,
                         cudaFuncAttributeMaxDynamicSharedMemorySize, smem1);
    cudaFuncSetAttribute(gemm_mma<64, true>,
                         cudaFuncAttributeMaxDynamicSharedMemorySize, smem2);

    const int gblk         = (NNODE + 127) / 128;   // 782
    const int node_blk     = (NNODE + 255) / 256;
    const int edge_blocks  = (NEDGE + 255) / 256;
    const int eplus_blocks = (EPLUS + 255) / 256;
    const int gath_blocks  = (NNODE + 7) / 8;

    // ----- CSR build -----
    init_kernel<<<node_blk, 256>>>();
    deg_count_kernel<<<edge_blocks, 256>>>(ei);
    scan1_kernel<<<NBLK_SCAN, 1024>>>();
    scan2_kernel<<<1, 128>>>();
    scan3_kernel<<<node_blk, 256>>>();
    fill_kernel<<<eplus_blocks, 256>>>(ei);

    // ----- layer 1 -----
    gemm_mma<128, false><<<gblk, 256, smem1>>>(x, W1, nullptr, as1, ad1,
                                               h1hp, es1p, ed1p, NNODE);
    gather1_kernel<<<gath_blocks, 256>>>();

    // ----- layer 2 -----
    gemm_mma<64, true><<<gblk, 128, smem2>>>(agg1p, W2, b1, as2, ad2,
                                             h2hp, es2p, ed2p, NNODE);
    gather2_kernel<<<gath_blocks, 256>>>(batch);

    // ----- decoder -----
    mlp_kernel<<<1, 256>>>(batch, b2, dw1, db1, dw2, db2, out);
}